// round 1
// baseline (speedup 1.0000x reference)
#include <cuda_runtime.h>
#include <cuda_bf16.h>

#define NPTS 1024
#define KPOS 512
#define KSEL 32

// One CTA per submap. 1024 threads.
// Phase A: key = (bits(sqrt(px^2+py^2)) << 32) | point_index   (ascending sort == jax top_k(-dist) order)
// Phase B: bitonic sort 1024 keys in shared memory
// Phase C: FPS over first 512 sorted points (start at rank 0), 31 argmax steps, ties -> lowest index
// Phase D: MLP (32->16->8->1, relu/relu/softplus) only for the 32 selected points
__global__ __launch_bounds__(1024, 2)
void detector_kernel(const float* __restrict__ x,
                     const float* __restrict__ pos,
                     const float* __restrict__ W1, const float* __restrict__ b1,
                     const float* __restrict__ W2, const float* __restrict__ b2,
                     const float* __restrict__ W3, const float* __restrict__ b3,
                     float* __restrict__ out_w, float* __restrict__ out_i)
{
    __shared__ unsigned long long skey[NPTS];
    __shared__ float psx[KPOS], psy[KPOS], psz[KPOS];
    __shared__ unsigned long long wred[32];
    __shared__ int selrank[KSEL];
    __shared__ int sbcast;
    __shared__ float sW1[32 * 16];
    __shared__ float sb1[16];
    __shared__ float sW2[16 * 8];
    __shared__ float sb2[8];
    __shared__ float sW3[8];
    __shared__ float sb3v;

    const int t = threadIdx.x;
    const int b = blockIdx.x;
    const long base = (long)b * NPTS;

    // ---- stage MLP params into smem (tiny) ----
    if (t < 512)            sW1[t] = W1[t];
    else if (t < 528)       sb1[t - 512] = b1[t - 512];
    else if (t < 656)       sW2[t - 528] = W2[t - 528];
    else if (t < 664)       sb2[t - 656] = b2[t - 656];
    else if (t < 672)       sW3[t - 664] = W3[t - 664];
    else if (t == 672)      sb3v = b3[0];

    // ---- Phase A: per-point key (no FMA contraction; match XLA mul/mul/add/sqrt) ----
    {
        float px = pos[3 * (base + t) + 0];
        float py = pos[3 * (base + t) + 1];
        float d2 = __fadd_rn(__fmul_rn(px, px), __fmul_rn(py, py));
        float dist = __fsqrt_rn(d2);
        skey[t] = (((unsigned long long)__float_as_uint(dist)) << 32) | (unsigned int)t;
    }
    __syncthreads();

    // ---- Phase B: bitonic sort ascending (dist, then index) ----
    for (int k = 2; k <= NPTS; k <<= 1) {
        for (int j = k >> 1; j > 0; j >>= 1) {
            int ixj = t ^ j;
            if (ixj > t) {
                unsigned long long a = skey[t];
                unsigned long long c = skey[ixj];
                bool up = ((t & k) == 0);
                if ((a > c) == up) { skey[t] = c; skey[ixj] = a; }
            }
            __syncthreads();
        }
    }

    // ---- load selected-512 positions ----
    float mx = 0.f, my = 0.f, mz = 0.f;
    if (t < KPOS) {
        int o = (int)(skey[t] & 0xFFFFFFFFull);
        long g = base + o;
        mx = pos[3 * g + 0];
        my = pos[3 * g + 1];
        mz = pos[3 * g + 2];
        psx[t] = mx; psy[t] = my; psz[t] = mz;
    }
    __syncthreads();

    // ---- Phase C: farthest point sampling ----
    float md = -1.0f;
    {
        float q0x = psx[0], q0y = psy[0], q0z = psz[0];
        if (t < KPOS) {
            float dx = __fadd_rn(mx, -q0x);
            float dy = __fadd_rn(my, -q0y);
            float dz = __fadd_rn(mz, -q0z);
            md = __fadd_rn(__fadd_rn(__fmul_rn(dx, dx), __fmul_rn(dy, dy)), __fmul_rn(dz, dz));
        }
    }
    if (t == 0) selrank[0] = 0;
    int cur = 0;

    for (int step = 1; step < KSEL; step++) {
        float qx = psx[cur], qy = psy[cur], qz = psz[cur];
        if (t < KPOS) {
            float dx = __fadd_rn(mx, -qx);
            float dy = __fadd_rn(my, -qy);
            float dz = __fadd_rn(mz, -qz);
            float d2 = __fadd_rn(__fadd_rn(__fmul_rn(dx, dx), __fmul_rn(dy, dy)), __fmul_rn(dz, dz));
            md = fminf(md, d2);
        }
        // pack: (md_bits << 32) | ~tid  -> max pack = max value, ties -> lowest index
        unsigned long long pack = 0ull;
        if (t < KPOS)
            pack = (((unsigned long long)__float_as_uint(md)) << 32) | (unsigned int)(~(unsigned int)t);

        #pragma unroll
        for (int off = 16; off > 0; off >>= 1) {
            unsigned long long o2 = __shfl_xor_sync(0xFFFFFFFFu, pack, off);
            if (o2 > pack) pack = o2;
        }
        if ((t & 31) == 0) wred[t >> 5] = pack;
        __syncthreads();
        if (t < 32) {
            unsigned long long v = wred[t];
            #pragma unroll
            for (int off = 16; off > 0; off >>= 1) {
                unsigned long long o2 = __shfl_xor_sync(0xFFFFFFFFu, v, off);
                if (o2 > v) v = o2;
            }
            if (t == 0) {
                int c = (int)(~(unsigned int)(v & 0xFFFFFFFFull));
                sbcast = c;
                selrank[step] = c;
            }
        }
        __syncthreads();
        cur = sbcast;
    }

    // ---- Phase D: MLP only for the 32 selected points ----
    if (t < KSEL) {
        int rank = selrank[t];
        int o = (int)(skey[rank] & 0xFFFFFFFFull);
        long g = base + o;
        const float* xr = x + g * 32;

        float h1[16];
        #pragma unroll
        for (int k2 = 0; k2 < 16; k2++) h1[k2] = sb1[k2];
        #pragma unroll
        for (int i = 0; i < 32; i++) {
            float xi = __ldg(xr + i);
            #pragma unroll
            for (int k2 = 0; k2 < 16; k2++)
                h1[k2] = fmaf(xi, sW1[i * 16 + k2], h1[k2]);
        }
        #pragma unroll
        for (int k2 = 0; k2 < 16; k2++) h1[k2] = fmaxf(h1[k2], 0.f);

        float h2[8];
        #pragma unroll
        for (int k2 = 0; k2 < 8; k2++) h2[k2] = sb2[k2];
        #pragma unroll
        for (int j = 0; j < 16; j++) {
            float hj = h1[j];
            #pragma unroll
            for (int k2 = 0; k2 < 8; k2++)
                h2[k2] = fmaf(hj, sW2[j * 8 + k2], h2[k2]);
        }
        float acc = sb3v;
        #pragma unroll
        for (int j = 0; j < 8; j++)
            acc = fmaf(fmaxf(h2[j], 0.f), sW3[j], acc);

        // softplus: max(x,0) + log1p(exp(-|x|))
        float s = fmaxf(acc, 0.f) + log1pf(expf(-fabsf(acc)));

        out_w[b * KSEL + t] = s;
        out_i[b * KSEL + t] = (float)o;
    }
}

extern "C" void kernel_launch(void* const* d_in, const int* in_sizes, int n_in,
                              void* d_out, int out_size)
{
    const float* x   = (const float*)d_in[0];
    const float* pos = (const float*)d_in[1];
    // d_in[2] = batch (unused; regular layout)
    const float* W1 = (const float*)d_in[3];
    const float* b1 = (const float*)d_in[4];
    const float* W2 = (const float*)d_in[5];
    const float* b2 = (const float*)d_in[6];
    const float* W3 = (const float*)d_in[7];
    const float* b3 = (const float*)d_in[8];

    int B = in_sizes[2] / NPTS;   // 2048
    float* out_w = (float*)d_out;
    float* out_i = out_w + (size_t)B * KSEL;

    detector_kernel<<<B, NPTS>>>(x, pos, W1, b1, W2, b2, W3, b3, out_w, out_i);
}

// round 2
// speedup vs baseline: 1.0483x; 1.0483x over previous
#include <cuda_runtime.h>
#include <cuda_bf16.h>

#define NPTS 1024
#define KPOS 512
#define KSEL 32
#define FULLMASK 0xFFFFFFFFu

// One CTA (1024 threads) per submap.
// Phase A: per-point key = fp32 bits of sqrt(px^2+py^2) (non-fused, matches XLA)
// Phase B: radix-select the KPOS-th smallest (dist, idx) -> membership of closest-512 set
// Phase C: deterministic compaction of selected points into smem (slot order = index order)
// Phase D: FPS (31 steps), argmax via redux.sync + 1 barrier/step, ties -> lowest index
// Phase E: MLP (32->16->8->1, relu/relu/softplus) only for the 32 selected points
__global__ __launch_bounds__(1024, 2)
void detector_kernel(const float* __restrict__ x,
                     const float* __restrict__ pos,
                     const float* __restrict__ W1, const float* __restrict__ b1,
                     const float* __restrict__ W2, const float* __restrict__ b2,
                     const float* __restrict__ W3, const float* __restrict__ b3,
                     float* __restrict__ out_w, float* __restrict__ out_i)
{
    __shared__ unsigned int hist[2048];
    __shared__ float qsx[KPOS], qsy[KPOS], qsz[KPOS];
    __shared__ unsigned int qdk[KPOS];
    __shared__ int qidx[KPOS];
    __shared__ int selslot[KSEL];
    __shared__ unsigned int sstate[4];   // [0]=prefix/T  [1]=kth/r  [2]=index cut
    __shared__ unsigned int wv[2][32];
    __shared__ unsigned int wsl[2][32];
    __shared__ int wsum[32];
    __shared__ float sW1[512]; __shared__ float sb1[16];
    __shared__ float sW2[128]; __shared__ float sb2[8];
    __shared__ float sW3[8];   __shared__ float sb3v;

    const int t = threadIdx.x;
    const int w = t >> 5, lane = t & 31;
    const int b = blockIdx.x;
    const long base = (long)b * NPTS;

    // ---- stage MLP params ----
    if (t < 512)       sW1[t] = W1[t];
    else if (t < 528)  sb1[t-512] = b1[t-512];
    else if (t < 656)  sW2[t-528] = W2[t-528];
    else if (t < 664)  sb2[t-656] = b2[t-656];
    else if (t < 672)  sW3[t-664] = W3[t-664];
    else if (t == 672) sb3v = b3[0];
    if (t == 0) { sstate[0] = 0u; sstate[1] = KPOS; }

    // ---- Phase A: own point + key ----
    const float px = pos[3*(base+t)+0];
    const float py = pos[3*(base+t)+1];
    const float pz = pos[3*(base+t)+2];
    const unsigned int kb =
        __float_as_uint(__fsqrt_rn(__fadd_rn(__fmul_rn(px,px), __fmul_rn(py,py))));

    // ---- Phase B: radix select KPOS-th smallest (kb, t) ----
    {
        const int shifts[3] = {21, 10, 0};
        const int bitsv [3] = {11, 11, 10};
        #pragma unroll 1
        for (int p = 0; p < 3; p++) {
            const int shift = shifts[p];
            const int nb = 1 << bitsv[p];
            hist[t] = 0u; hist[t + 1024] = 0u;
            __syncthreads();
            const unsigned int prefix = sstate[0], kth = sstate[1];
            const int sb = shift + bitsv[p];
            const unsigned int hm = (sb >= 32) ? 0u : (0xFFFFFFFFu << sb);
            if ((kb & hm) == prefix)
                atomicAdd(&hist[(kb >> shift) & (nb - 1)], 1u);
            __syncthreads();
            if (t < 32) {
                const int per = nb >> 5;
                unsigned int s = 0;
                for (int i = 0; i < per; i++) s += hist[t * per + i];
                unsigned int inc = s;
                #pragma unroll
                for (int d = 1; d < 32; d <<= 1) {
                    unsigned int v = __shfl_up_sync(FULLMASK, inc, d);
                    if (t >= d) inc += v;
                }
                const unsigned int excl = inc - s;
                if (kth > excl && kth <= inc) {
                    unsigned int rem = kth - excl, c2 = 0;
                    for (int i = 0; i < per; i++) {
                        unsigned int h = hist[t * per + i];
                        if (c2 + h >= rem) {
                            sstate[0] = prefix | ((unsigned int)(t * per + i) << shift);
                            sstate[1] = rem - c2;
                            break;
                        }
                        c2 += h;
                    }
                }
            }
            __syncthreads();
        }
    }
    const unsigned int T = sstate[0];
    const unsigned int r = sstate[1];

    // ---- boundary tie pass: r-th smallest index among kb == T ----
    hist[t] = (kb == T) ? 1u : 0u;
    __syncthreads();
    if (t < 32) {
        unsigned int s = 0;
        for (int i = 0; i < 32; i++) s += hist[t * 32 + i];
        unsigned int inc = s;
        #pragma unroll
        for (int d = 1; d < 32; d <<= 1) {
            unsigned int v = __shfl_up_sync(FULLMASK, inc, d);
            if (t >= d) inc += v;
        }
        const unsigned int excl = inc - s;
        if (r > excl && r <= inc) {
            unsigned int rem = r - excl, c2 = 0;
            for (int i = 0; i < 32; i++) {
                unsigned int h = hist[t * 32 + i];
                if (c2 + h >= rem) { sstate[2] = (unsigned int)(t * 32 + i); break; }
                c2 += h;
            }
        }
    }
    __syncthreads();
    const unsigned int cut = sstate[2];
    const bool sel = (kb < T) || (kb == T && (unsigned int)t <= cut);

    // ---- Phase C: compaction (slot order == index order) ----
    const unsigned int bal = __ballot_sync(FULLMASK, sel);
    if (lane == 0) wsum[w] = __popc(bal);
    __syncthreads();
    if (t < 32) {
        int sv = wsum[t];
        int inc = sv;
        #pragma unroll
        for (int d = 1; d < 32; d <<= 1) {
            int v = __shfl_up_sync(FULLMASK, inc, d);
            if (t >= d) inc += v;
        }
        wsum[t] = inc - sv;
    }
    __syncthreads();
    if (sel) {
        int slot = wsum[w] + __popc(bal & ((1u << lane) - 1u));
        qsx[slot] = px; qsy[slot] = py; qsz[slot] = pz;
        qdk[slot] = kb; qidx[slot] = t;
    }
    __syncthreads();

    // ---- Phase D: FPS over 512 selected; thread t<512 owns slot t ----
    float qx = 0.f, qy = 0.f, qz = 0.f;
    unsigned int qk = 0xFFFFFFFFu;
    if (t < KPOS) { qx = qsx[t]; qy = qsy[t]; qz = qsz[t]; qk = qdk[t]; }

    // start = argmin (dist, index) over selected set (= global closest point)
    {
        unsigned int wm = __reduce_min_sync(FULLMASK, qk);
        unsigned int ws = __reduce_min_sync(
            FULLMASK, (t < KPOS && qk == wm) ? (unsigned int)t : 0xFFFFFFFFu);
        if (lane == 0) { wv[0][w] = wm; wsl[0][w] = ws; }
    }
    __syncthreads();
    int cur;
    {
        unsigned int vv = (lane < 16) ? wv[0][lane] : 0xFFFFFFFFu;
        unsigned int mm = __reduce_min_sync(FULLMASK, vv);
        unsigned int ss = (lane < 16 && vv == mm) ? wsl[0][lane] : 0xFFFFFFFFu;
        cur = (int)__reduce_min_sync(FULLMASK, ss);
    }
    if (t == 0) selslot[0] = cur;

    float md = -1.f;
    {
        float ax = qsx[cur], ay = qsy[cur], az = qsz[cur];
        if (t < KPOS) {
            float dx = __fadd_rn(qx, -ax), dy = __fadd_rn(qy, -ay), dz = __fadd_rn(qz, -az);
            md = __fadd_rn(__fadd_rn(__fmul_rn(dx,dx), __fmul_rn(dy,dy)), __fmul_rn(dz,dz));
        }
    }

    #pragma unroll 1
    for (int step = 1; step < KSEL; step++) {
        const int pb = step & 1;
        const unsigned int mv = (t < KPOS) ? __float_as_uint(md) : 0u;
        const unsigned int wm = __reduce_max_sync(FULLMASK, mv);
        const unsigned int ws = __reduce_min_sync(
            FULLMASK, (t < KPOS && mv == wm) ? (unsigned int)t : 0xFFFFFFFFu);
        if (lane == 0) { wv[pb][w] = wm; wsl[pb][w] = ws; }
        __syncthreads();
        const unsigned int vv = (lane < 16) ? wv[pb][lane] : 0u;
        const unsigned int mm = __reduce_max_sync(FULLMASK, vv);
        const unsigned int ss = (lane < 16 && vv == mm) ? wsl[pb][lane] : 0xFFFFFFFFu;
        cur = (int)__reduce_min_sync(FULLMASK, ss);
        if (t == 0) selslot[step] = cur;
        const float ax = qsx[cur], ay = qsy[cur], az = qsz[cur];
        if (t < KPOS) {
            float dx = __fadd_rn(qx, -ax), dy = __fadd_rn(qy, -ay), dz = __fadd_rn(qz, -az);
            float d2 = __fadd_rn(__fadd_rn(__fmul_rn(dx,dx), __fmul_rn(dy,dy)), __fmul_rn(dz,dz));
            md = fminf(md, d2);
        }
    }
    __syncthreads();

    // ---- Phase E: MLP for the 32 selected points ----
    if (t < KSEL) {
        const int slot = selslot[t];
        const int o = qidx[slot];
        const long g = base + o;
        const float* xr = x + g * 32;

        float h1[16];
        #pragma unroll
        for (int k2 = 0; k2 < 16; k2++) h1[k2] = sb1[k2];
        #pragma unroll
        for (int i = 0; i < 32; i++) {
            float xi = __ldg(xr + i);
            #pragma unroll
            for (int k2 = 0; k2 < 16; k2++)
                h1[k2] = fmaf(xi, sW1[i * 16 + k2], h1[k2]);
        }
        #pragma unroll
        for (int k2 = 0; k2 < 16; k2++) h1[k2] = fmaxf(h1[k2], 0.f);

        float h2[8];
        #pragma unroll
        for (int k2 = 0; k2 < 8; k2++) h2[k2] = sb2[k2];
        #pragma unroll
        for (int j = 0; j < 16; j++) {
            float hj = h1[j];
            #pragma unroll
            for (int k2 = 0; k2 < 8; k2++)
                h2[k2] = fmaf(hj, sW2[j * 8 + k2], h2[k2]);
        }
        float acc = sb3v;
        #pragma unroll
        for (int j = 0; j < 8; j++)
            acc = fmaf(fmaxf(h2[j], 0.f), sW3[j], acc);

        float s = fmaxf(acc, 0.f) + log1pf(expf(-fabsf(acc)));

        out_w[b * KSEL + t] = s;
        out_i[b * KSEL + t] = (float)o;
    }
}

extern "C" void kernel_launch(void* const* d_in, const int* in_sizes, int n_in,
                              void* d_out, int out_size)
{
    const float* x   = (const float*)d_in[0];
    const float* pos = (const float*)d_in[1];
    // d_in[2] = batch (unused; regular layout)
    const float* W1 = (const float*)d_in[3];
    const float* b1 = (const float*)d_in[4];
    const float* W2 = (const float*)d_in[5];
    const float* b2 = (const float*)d_in[6];
    const float* W3 = (const float*)d_in[7];
    const float* b3 = (const float*)d_in[8];

    int B = in_sizes[2] / NPTS;   // 2048
    float* out_w = (float*)d_out;
    float* out_i = out_w + (size_t)B * KSEL;

    detector_kernel<<<B, NPTS>>>(x, pos, W1, b1, W2, b2, W3, b3, out_w, out_i);
}

// round 3
// speedup vs baseline: 1.9453x; 1.8556x over previous
#include <cuda_runtime.h>
#include <cuda_bf16.h>

#define NPTS 1024
#define KPOS 512
#define KSEL 32
#define B_MAX 2048
#define FULLMASK 0xFFFFFFFFu

// scratch: compacted selected points per submap (planar) + FPS seed slot
__device__ float g_sx[B_MAX * KPOS];
__device__ float g_sy[B_MAX * KPOS];
__device__ float g_sz[B_MAX * KPOS];
__device__ int   g_si[B_MAX * KPOS];
__device__ int   g_seed[B_MAX];

// ============================================================================
// Kernel 1: per-submap selection of the 512 xy-closest points (exact jax
// top_k(-dist) semantics incl. ties), compaction in index order, seed argmin.
// ============================================================================
__global__ __launch_bounds__(1024, 2)
void select_kernel(const float* __restrict__ pos)
{
    __shared__ unsigned int hist[2048];
    __shared__ unsigned int sstate[4];   // [0]=prefix/T  [1]=kth/r  [2]=index cut
    __shared__ int wsum[32];
    __shared__ unsigned long long wpk[32];
    __shared__ unsigned long long spk;

    const int t = threadIdx.x;
    const int w = t >> 5, lane = t & 31;
    const int b = blockIdx.x;
    const long base = (long)b * NPTS;

    if (t == 0) { sstate[0] = 0u; sstate[1] = KPOS; }

    // ---- per-point key: sqrt(px^2+py^2), non-fused (match XLA) ----
    const float px = pos[3*(base+t)+0];
    const float py = pos[3*(base+t)+1];
    const float pz = pos[3*(base+t)+2];
    const unsigned int kb =
        __float_as_uint(__fsqrt_rn(__fadd_rn(__fmul_rn(px,px), __fmul_rn(py,py))));

    // ---- radix select KPOS-th smallest ----
    {
        const int shifts[3] = {21, 10, 0};
        const int bitsv [3] = {11, 11, 10};
        #pragma unroll 1
        for (int p = 0; p < 3; p++) {
            const int shift = shifts[p];
            const int nb = 1 << bitsv[p];
            hist[t] = 0u; hist[t + 1024] = 0u;
            __syncthreads();
            const unsigned int prefix = sstate[0], kth = sstate[1];
            const int sb = shift + bitsv[p];
            const unsigned int hm = (sb >= 32) ? 0u : (0xFFFFFFFFu << sb);
            if ((kb & hm) == prefix)
                atomicAdd(&hist[(kb >> shift) & (nb - 1)], 1u);
            __syncthreads();
            if (t < 32) {
                const int per = nb >> 5;
                unsigned int s = 0;
                for (int i = 0; i < per; i++) s += hist[t * per + i];
                unsigned int inc = s;
                #pragma unroll
                for (int d = 1; d < 32; d <<= 1) {
                    unsigned int v = __shfl_up_sync(FULLMASK, inc, d);
                    if (t >= d) inc += v;
                }
                const unsigned int excl = inc - s;
                if (kth > excl && kth <= inc) {
                    unsigned int rem = kth - excl, c2 = 0;
                    for (int i = 0; i < per; i++) {
                        unsigned int h = hist[t * per + i];
                        if (c2 + h >= rem) {
                            sstate[0] = prefix | ((unsigned int)(t * per + i) << shift);
                            sstate[1] = rem - c2;
                            break;
                        }
                        c2 += h;
                    }
                }
            }
            __syncthreads();
        }
    }
    const unsigned int T = sstate[0];
    const unsigned int r = sstate[1];

    // ---- boundary tie pass: r-th smallest index among kb == T ----
    hist[t] = (kb == T) ? 1u : 0u;
    __syncthreads();
    if (t < 32) {
        unsigned int s = 0;
        for (int i = 0; i < 32; i++) s += hist[t * 32 + i];
        unsigned int inc = s;
        #pragma unroll
        for (int d = 1; d < 32; d <<= 1) {
            unsigned int v = __shfl_up_sync(FULLMASK, inc, d);
            if (t >= d) inc += v;
        }
        const unsigned int excl = inc - s;
        if (r > excl && r <= inc) {
            unsigned int rem = r - excl, c2 = 0;
            for (int i = 0; i < 32; i++) {
                unsigned int h = hist[t * 32 + i];
                if (c2 + h >= rem) { sstate[2] = (unsigned int)(t * 32 + i); break; }
                c2 += h;
            }
        }
    }
    __syncthreads();
    const unsigned int cut = sstate[2];
    const bool sel = (kb < T) || (kb == T && (unsigned int)t <= cut);

    // ---- compaction prefix (slot order == index order) ----
    const unsigned int bal = __ballot_sync(FULLMASK, sel);
    if (lane == 0) wsum[w] = __popc(bal);

    // ---- block argmin of (kb, t) for FPS seed (overlap with compaction) ----
    unsigned long long pk = (((unsigned long long)kb) << 32) | (unsigned int)t;
    #pragma unroll
    for (int off = 16; off > 0; off >>= 1) {
        unsigned long long o2 = __shfl_xor_sync(FULLMASK, pk, off);
        if (o2 < pk) pk = o2;
    }
    if (lane == 0) wpk[w] = pk;
    __syncthreads();
    if (t < 32) {
        int sv = wsum[t];
        int inc = sv;
        #pragma unroll
        for (int d = 1; d < 32; d <<= 1) {
            int v = __shfl_up_sync(FULLMASK, inc, d);
            if (t >= d) inc += v;
        }
        wsum[t] = inc - sv;

        unsigned long long v2 = wpk[t];
        #pragma unroll
        for (int off = 16; off > 0; off >>= 1) {
            unsigned long long o2 = __shfl_xor_sync(FULLMASK, v2, off);
            if (o2 < v2) v2 = o2;
        }
        if (t == 0) spk = v2;
    }
    __syncthreads();

    if (sel) {
        const int slot = wsum[w] + __popc(bal & ((1u << lane) - 1u));
        const int o = b * KPOS + slot;
        g_sx[o] = px; g_sy[o] = py; g_sz[o] = pz; g_si[o] = t;
        if ((unsigned int)t == (unsigned int)(spk & 0xFFFFFFFFull))
            g_seed[b] = slot;
    }
}

// ============================================================================
// Kernel 2: one warp per submap. FPS (31 steps, warp-only sync) + per-lane MLP.
// Lane owns 16 points in registers; query point broadcast from smem float4.
// ============================================================================
__global__ __launch_bounds__(128)
void fps_mlp_kernel(const float* __restrict__ x,
                    const float* __restrict__ W1, const float* __restrict__ b1,
                    const float* __restrict__ W2, const float* __restrict__ b2,
                    const float* __restrict__ W3, const float* __restrict__ b3,
                    float* __restrict__ out_w, float* __restrict__ out_i)
{
    __shared__ float4 qpos[4 * KPOS];
    __shared__ float sW1[512]; __shared__ float sb1[16];
    __shared__ float sW2[128]; __shared__ float sb2[8];
    __shared__ float sW3[8];   __shared__ float sb3v;

    const int tid = threadIdx.x;
    // stage MLP params
    for (int i = tid; i < 512; i += 128) sW1[i] = W1[i];
    if (tid < 128) sW2[tid] = W2[tid];
    if (tid < 16)  sb1[tid] = b1[tid];
    if (tid < 8)   sb2[tid] = b2[tid];
    if (tid < 8)   sW3[tid] = W3[tid];
    if (tid == 0)  sb3v = b3[0];
    __syncthreads();

    const int w = tid >> 5, lane = tid & 31;
    const int b = blockIdx.x * 4 + w;

    const float* bx = g_sx + (size_t)b * KPOS;
    const float* by = g_sy + (size_t)b * KPOS;
    const float* bz = g_sz + (size_t)b * KPOS;
    const int*   bi = g_si + (size_t)b * KPOS;
    float4* qp = qpos + w * KPOS;

    float px[16], py[16], pz[16], md[16];
    #pragma unroll
    for (int j = 0; j < 16; j++) {
        const int s = j * 32 + lane;
        const float X = bx[s], Y = by[s], Z = bz[s];
        const int   I = bi[s];
        px[j] = X; py[j] = Y; pz[j] = Z;
        qp[s] = make_float4(X, Y, Z, __int_as_float(I));
    }
    __syncwarp();

    const int s0 = g_seed[b];
    float4 q = qp[s0];
    int mysel = s0;   // lane 'step' records the step'th selection; step 0 = seed

    #pragma unroll
    for (int j = 0; j < 16; j++) {
        const float dx = __fadd_rn(px[j], -q.x);
        const float dy = __fadd_rn(py[j], -q.y);
        const float dz = __fadd_rn(pz[j], -q.z);
        md[j] = __fadd_rn(__fadd_rn(__fmul_rn(dx,dx), __fmul_rn(dy,dy)), __fmul_rn(dz,dz));
    }

    #pragma unroll 1
    for (int step = 1; step < KSEL; step++) {
        // local argmax (strict > keeps lowest slot within lane)
        float best = md[0]; int bs = lane;
        #pragma unroll
        for (int j = 1; j < 16; j++)
            if (md[j] > best) { best = md[j]; bs = j * 32 + lane; }
        // warp argmax, ties -> lowest slot (nonneg floats compare as uints)
        const unsigned int bb = __float_as_uint(best);
        const unsigned int wm = __reduce_max_sync(FULLMASK, bb);
        const unsigned int cand = (bb == wm) ? (unsigned int)bs : 0xFFFFFFFFu;
        const int cur = (int)__reduce_min_sync(FULLMASK, cand);
        if (lane == step) mysel = cur;
        q = qp[cur];
        #pragma unroll
        for (int j = 0; j < 16; j++) {
            const float dx = __fadd_rn(px[j], -q.x);
            const float dy = __fadd_rn(py[j], -q.y);
            const float dz = __fadd_rn(pz[j], -q.z);
            const float d2 = __fadd_rn(__fadd_rn(__fmul_rn(dx,dx), __fmul_rn(dy,dy)), __fmul_rn(dz,dz));
            md[j] = fminf(md[j], d2);
        }
    }

    // ---- per-lane MLP for its selected point ----
    const float4 qs = qp[mysel];
    const int o = __float_as_int(qs.w);
    const float* xr = x + ((long)b * NPTS + o) * 32;

    float h1[16];
    #pragma unroll
    for (int k2 = 0; k2 < 16; k2++) h1[k2] = sb1[k2];
    #pragma unroll
    for (int i = 0; i < 32; i += 4) {
        const float4 xv = *(const float4*)(xr + i);
        #pragma unroll
        for (int k2 = 0; k2 < 16; k2++) {
            h1[k2] = fmaf(xv.x, sW1[(i+0) * 16 + k2], h1[k2]);
            h1[k2] = fmaf(xv.y, sW1[(i+1) * 16 + k2], h1[k2]);
            h1[k2] = fmaf(xv.z, sW1[(i+2) * 16 + k2], h1[k2]);
            h1[k2] = fmaf(xv.w, sW1[(i+3) * 16 + k2], h1[k2]);
        }
    }
    #pragma unroll
    for (int k2 = 0; k2 < 16; k2++) h1[k2] = fmaxf(h1[k2], 0.f);

    float h2[8];
    #pragma unroll
    for (int k2 = 0; k2 < 8; k2++) h2[k2] = sb2[k2];
    #pragma unroll
    for (int j = 0; j < 16; j++) {
        const float hj = h1[j];
        #pragma unroll
        for (int k2 = 0; k2 < 8; k2++)
            h2[k2] = fmaf(hj, sW2[j * 8 + k2], h2[k2]);
    }
    float acc = sb3v;
    #pragma unroll
    for (int j = 0; j < 8; j++)
        acc = fmaf(fmaxf(h2[j], 0.f), sW3[j], acc);

    const float s = fmaxf(acc, 0.f) + log1pf(expf(-fabsf(acc)));

    out_w[b * KSEL + lane] = s;
    out_i[b * KSEL + lane] = (float)o;
}

extern "C" void kernel_launch(void* const* d_in, const int* in_sizes, int n_in,
                              void* d_out, int out_size)
{
    const float* x   = (const float*)d_in[0];
    const float* pos = (const float*)d_in[1];
    // d_in[2] = batch (unused; regular layout)
    const float* W1 = (const float*)d_in[3];
    const float* b1 = (const float*)d_in[4];
    const float* W2 = (const float*)d_in[5];
    const float* b2 = (const float*)d_in[6];
    const float* W3 = (const float*)d_in[7];
    const float* b3 = (const float*)d_in[8];

    const int B = in_sizes[2] / NPTS;   // 2048
    float* out_w = (float*)d_out;
    float* out_i = out_w + (size_t)B * KSEL;

    select_kernel<<<B, NPTS>>>(pos);
    fps_mlp_kernel<<<B / 4, 128>>>(x, W1, b1, W2, b2, W3, b3, out_w, out_i);
}

// round 4
// speedup vs baseline: 4.0174x; 2.0652x over previous
#include <cuda_runtime.h>
#include <cuda_bf16.h>

#define NPTS 1024
#define KPOS 512
#define KSEL 32
#define B_MAX 2048
#define FULLMASK 0xFFFFFFFFu

// scratch: compacted selected points per submap (x,y,z,idx-bits) + FPS seed slot
__device__ float4 g_pts[B_MAX * KPOS];
__device__ int    g_seed[B_MAX];

// ============================================================================
// Kernel 1: per-submap selection of the 512 xy-closest points (exact jax
// top_k(-dist) semantics incl. ties). Fully parallel radix-select: per-pass
// 2048-bin histogram + block prefix scan (no serial single-warp sections).
// ============================================================================
__global__ __launch_bounds__(1024, 2)
void select_kernel(const float* __restrict__ pos)
{
    __shared__ unsigned int hist[2048];
    __shared__ unsigned int sstate[4];   // [0]=prefix/T  [1]=kth/r  [2]=index cut
    __shared__ unsigned int wsum[32];
    __shared__ unsigned long long wpk[32];
    __shared__ unsigned long long spk;

    const int t = threadIdx.x;
    const int w = t >> 5, lane = t & 31;
    const int b = blockIdx.x;
    const long base = (long)b * NPTS;

    if (t == 0) { sstate[0] = 0u; sstate[1] = KPOS; }

    // ---- per-point key: sqrt(px^2+py^2), non-fused (match XLA) ----
    const float px = pos[3*(base+t)+0];
    const float py = pos[3*(base+t)+1];
    const float pz = pos[3*(base+t)+2];
    const unsigned int kb =
        __float_as_uint(__fsqrt_rn(__fadd_rn(__fmul_rn(px,px), __fmul_rn(py,py))));

    // ---- radix select KPOS-th smallest: 3 passes (11/11/10 bits) ----
    {
        const int shifts[3] = {21, 10, 0};
        const int bitsv [3] = {11, 11, 10};
        #pragma unroll 1
        for (int p = 0; p < 3; p++) {
            const int shift = shifts[p];
            const int nb = 1 << bitsv[p];
            hist[t] = 0u; hist[t + 1024] = 0u;
            __syncthreads();
            const unsigned int prefix = sstate[0], kth = sstate[1];
            const int sb = shift + bitsv[p];
            const unsigned int hm = (sb >= 32) ? 0u : (0xFFFFFFFFu << sb);
            if ((kb & hm) == prefix)
                atomicAdd(&hist[(kb >> shift) & (nb - 1)], 1u);
            __syncthreads();

            // parallel prefix scan over 2048 bins: thread owns bins {2t, 2t+1}
            const unsigned int h0 = hist[2 * t];
            const unsigned int h1 = hist[2 * t + 1];
            const unsigned int s = h0 + h1;
            unsigned int inc = s;
            #pragma unroll
            for (int d = 1; d < 32; d <<= 1) {
                unsigned int v = __shfl_up_sync(FULLMASK, inc, d);
                if (lane >= d) inc += v;
            }
            if (lane == 31) wsum[w] = inc;
            __syncthreads();
            if (t < 32) {
                unsigned int wv = wsum[t];
                unsigned int winc = wv;
                #pragma unroll
                for (int d = 1; d < 32; d <<= 1) {
                    unsigned int v = __shfl_up_sync(FULLMASK, winc, d);
                    if (t >= d) winc += v;
                }
                wsum[t] = winc - wv;   // exclusive warp base
            }
            __syncthreads();
            const unsigned int base0 = wsum[w] + (inc - s);   // excl prefix of bin 2t
            // kth in (excl, incl] of exactly one non-empty bin
            if (kth > base0 && kth <= base0 + h0) {
                sstate[0] = prefix | ((unsigned int)(2 * t) << shift);
                sstate[1] = kth - base0;
            } else if (kth > base0 + h0 && kth <= base0 + h0 + h1) {
                sstate[0] = prefix | ((unsigned int)(2 * t + 1) << shift);
                sstate[1] = kth - base0 - h0;
            }
            __syncthreads();
        }
    }
    const unsigned int T = sstate[0];
    const unsigned int r = sstate[1];

    // ---- boundary tie pass: r-th smallest index among kb == T (parallel rank)
    const bool tied = (kb == T);
    {
        const unsigned int tb = __ballot_sync(FULLMASK, tied);
        if (lane == 0) wsum[w] = __popc(tb);
        __syncthreads();
        if (t < 32) {
            unsigned int wv = wsum[t];
            unsigned int winc = wv;
            #pragma unroll
            for (int d = 1; d < 32; d <<= 1) {
                unsigned int v = __shfl_up_sync(FULLMASK, winc, d);
                if (t >= d) winc += v;
            }
            wsum[t] = winc - wv;
        }
        __syncthreads();
        const unsigned int rank = wsum[w] + __popc(tb & ((1u << lane) - 1u));
        if (tied && rank == r - 1) sstate[2] = (unsigned int)t;
        __syncthreads();
    }
    const unsigned int cut = sstate[2];
    const bool sel = (kb < T) || (tied && (unsigned int)t <= cut);
    __syncthreads();   // wsum reuse below

    // ---- compaction prefix (slot order == index order) ----
    const unsigned int bal = __ballot_sync(FULLMASK, sel);
    if (lane == 0) wsum[w] = __popc(bal);

    // ---- block argmin of (kb, t) for FPS seed ----
    unsigned long long pk = (((unsigned long long)kb) << 32) | (unsigned int)t;
    #pragma unroll
    for (int off = 16; off > 0; off >>= 1) {
        unsigned long long o2 = __shfl_xor_sync(FULLMASK, pk, off);
        if (o2 < pk) pk = o2;
    }
    if (lane == 0) wpk[w] = pk;
    __syncthreads();
    if (t < 32) {
        unsigned int sv = wsum[t];
        unsigned int inc = sv;
        #pragma unroll
        for (int d = 1; d < 32; d <<= 1) {
            unsigned int v = __shfl_up_sync(FULLMASK, inc, d);
            if (t >= d) inc += v;
        }
        wsum[t] = inc - sv;

        unsigned long long v2 = wpk[t];
        #pragma unroll
        for (int off = 16; off > 0; off >>= 1) {
            unsigned long long o2 = __shfl_xor_sync(FULLMASK, v2, off);
            if (o2 < v2) v2 = o2;
        }
        if (t == 0) spk = v2;
    }
    __syncthreads();

    if (sel) {
        const int slot = (int)wsum[w] + __popc(bal & ((1u << lane) - 1u));
        g_pts[b * KPOS + slot] = make_float4(px, py, pz, __int_as_float(t));
        if ((unsigned int)t == (unsigned int)(spk & 0xFFFFFFFFull))
            g_seed[b] = slot;
    }
}

// ============================================================================
// Kernel 2: one warp per submap. FPS (31 steps, warp-only sync) + per-lane MLP.
// ============================================================================
__global__ __launch_bounds__(128)
void fps_mlp_kernel(const float* __restrict__ x,
                    const float* __restrict__ W1, const float* __restrict__ b1,
                    const float* __restrict__ W2, const float* __restrict__ b2,
                    const float* __restrict__ W3, const float* __restrict__ b3,
                    float* __restrict__ out_w, float* __restrict__ out_i)
{
    __shared__ float4 qpos[4 * KPOS];
    __shared__ float sW1[512]; __shared__ float sb1[16];
    __shared__ float sW2[128]; __shared__ float sb2[8];
    __shared__ float sW3[8];   __shared__ float sb3v;

    const int tid = threadIdx.x;
    for (int i = tid; i < 512; i += 128) sW1[i] = W1[i];
    if (tid < 128) sW2[tid] = W2[tid];
    if (tid < 16)  sb1[tid] = b1[tid];
    if (tid < 8)   sb2[tid] = b2[tid];
    if (tid < 8)   sW3[tid] = W3[tid];
    if (tid == 0)  sb3v = b3[0];
    __syncthreads();

    const int w = tid >> 5, lane = tid & 31;
    const int b = blockIdx.x * 4 + w;

    const float4* bp = g_pts + (size_t)b * KPOS;
    float4* qp = qpos + w * KPOS;

    float px[16], py[16], pz[16], md[16];
    #pragma unroll
    for (int j = 0; j < 16; j++) {
        const int s = j * 32 + lane;
        const float4 v = bp[s];
        px[j] = v.x; py[j] = v.y; pz[j] = v.z;
        qp[s] = v;
    }
    __syncwarp();

    const int s0 = g_seed[b];
    float4 q = qp[s0];
    int mysel = s0;   // lane 'step' records the step'th selection; step 0 = seed

    #pragma unroll
    for (int j = 0; j < 16; j++) {
        const float dx = __fadd_rn(px[j], -q.x);
        const float dy = __fadd_rn(py[j], -q.y);
        const float dz = __fadd_rn(pz[j], -q.z);
        md[j] = __fadd_rn(__fadd_rn(__fmul_rn(dx,dx), __fmul_rn(dy,dy)), __fmul_rn(dz,dz));
    }

    #pragma unroll 1
    for (int step = 1; step < KSEL; step++) {
        float best = md[0]; int bs = lane;
        #pragma unroll
        for (int j = 1; j < 16; j++)
            if (md[j] > best) { best = md[j]; bs = j * 32 + lane; }
        const unsigned int bb = __float_as_uint(best);
        const unsigned int wm = __reduce_max_sync(FULLMASK, bb);
        const unsigned int cand = (bb == wm) ? (unsigned int)bs : 0xFFFFFFFFu;
        const int cur = (int)__reduce_min_sync(FULLMASK, cand);
        if (lane == step) mysel = cur;
        q = qp[cur];
        #pragma unroll
        for (int j = 0; j < 16; j++) {
            const float dx = __fadd_rn(px[j], -q.x);
            const float dy = __fadd_rn(py[j], -q.y);
            const float dz = __fadd_rn(pz[j], -q.z);
            const float d2 = __fadd_rn(__fadd_rn(__fmul_rn(dx,dx), __fmul_rn(dy,dy)), __fmul_rn(dz,dz));
            md[j] = fminf(md[j], d2);
        }
    }

    // ---- per-lane MLP for its selected point ----
    const float4 qs = qp[mysel];
    const int o = __float_as_int(qs.w);
    const float* xr = x + ((long)b * NPTS + o) * 32;

    float h1[16];
    #pragma unroll
    for (int k2 = 0; k2 < 16; k2++) h1[k2] = sb1[k2];
    #pragma unroll
    for (int i = 0; i < 32; i += 4) {
        const float4 xv = *(const float4*)(xr + i);
        #pragma unroll
        for (int k2 = 0; k2 < 16; k2++) {
            h1[k2] = fmaf(xv.x, sW1[(i+0) * 16 + k2], h1[k2]);
            h1[k2] = fmaf(xv.y, sW1[(i+1) * 16 + k2], h1[k2]);
            h1[k2] = fmaf(xv.z, sW1[(i+2) * 16 + k2], h1[k2]);
            h1[k2] = fmaf(xv.w, sW1[(i+3) * 16 + k2], h1[k2]);
        }
    }
    #pragma unroll
    for (int k2 = 0; k2 < 16; k2++) h1[k2] = fmaxf(h1[k2], 0.f);

    float h2[8];
    #pragma unroll
    for (int k2 = 0; k2 < 8; k2++) h2[k2] = sb2[k2];
    #pragma unroll
    for (int j = 0; j < 16; j++) {
        const float hj = h1[j];
        #pragma unroll
        for (int k2 = 0; k2 < 8; k2++)
            h2[k2] = fmaf(hj, sW2[j * 8 + k2], h2[k2]);
    }
    float acc = sb3v;
    #pragma unroll
    for (int j = 0; j < 8; j++)
        acc = fmaf(fmaxf(h2[j], 0.f), sW3[j], acc);

    const float s = fmaxf(acc, 0.f) + log1pf(expf(-fabsf(acc)));

    out_w[b * KSEL + lane] = s;
    out_i[b * KSEL + lane] = (float)o;
}

extern "C" void kernel_launch(void* const* d_in, const int* in_sizes, int n_in,
                              void* d_out, int out_size)
{
    const float* x   = (const float*)d_in[0];
    const float* pos = (const float*)d_in[1];
    // d_in[2] = batch (unused; regular layout)
    const float* W1 = (const float*)d_in[3];
    const float* b1 = (const float*)d_in[4];
    const float* W2 = (const float*)d_in[5];
    const float* b2 = (const float*)d_in[6];
    const float* W3 = (const float*)d_in[7];
    const float* b3 = (const float*)d_in[8];

    const int B = in_sizes[2] / NPTS;   // 2048
    float* out_w = (float*)d_out;
    float* out_i = out_w + (size_t)B * KSEL;

    select_kernel<<<B, NPTS>>>(pos);
    fps_mlp_kernel<<<B / 4, 128>>>(x, W1, b1, W2, b2, W3, b3, out_w, out_i);
}

// round 5
// speedup vs baseline: 4.1476x; 1.0324x over previous
#include <cuda_runtime.h>
#include <cuda_bf16.h>

#define NPTS 1024
#define KPOS 512
#define KSEL 32
#define B_MAX 2048
#define FULLMASK 0xFFFFFFFFu

typedef unsigned long long ull;

// scratch: compacted selected points per submap (x,y,z,idx-bits) + FPS seed slot
__device__ float4 g_pts[B_MAX * KPOS];
__device__ int    g_seed[B_MAX];

// ---- packed f32x2 helpers (lanewise IEEE rn — bit-identical to scalar rn ops)
__device__ __forceinline__ ull pk2(float a, float b) {
    ull r; asm("mov.b64 %0, {%1, %2};" : "=l"(r) : "f"(a), "f"(b)); return r;
}
__device__ __forceinline__ void upk2(ull v, float& a, float& b) {
    asm("mov.b64 {%0, %1}, %2;" : "=f"(a), "=f"(b) : "l"(v));
}
__device__ __forceinline__ ull addx2(ull a, ull b) {
    ull r; asm("add.rn.f32x2 %0, %1, %2;" : "=l"(r) : "l"(a), "l"(b)); return r;
}
__device__ __forceinline__ ull mulx2(ull a, ull b) {
    ull r; asm("mul.rn.f32x2 %0, %1, %2;" : "=l"(r) : "l"(a), "l"(b)); return r;
}

// ============================================================================
// Kernel 1: per-submap selection of the 512 xy-closest points (exact jax
// top_k(-dist) semantics incl. ties). Radix select + closed-form compaction.
// ============================================================================
__global__ __launch_bounds__(1024, 2)
void select_kernel(const float* __restrict__ pos)
{
    __shared__ unsigned int hist[2048];
    __shared__ unsigned int sstate[2];   // [0]=prefix/T  [1]=kth/r
    __shared__ unsigned int wA[32], wB[32];
    __shared__ ull wpk[32];
    __shared__ ull spk;

    const int t = threadIdx.x;
    const int w = t >> 5, lane = t & 31;
    const int b = blockIdx.x;
    const long base = (long)b * NPTS;

    if (t == 0) { sstate[0] = 0u; sstate[1] = KPOS; }

    // ---- per-point key: sqrt(px^2+py^2), non-fused (match XLA) ----
    const float px = pos[3*(base+t)+0];
    const float py = pos[3*(base+t)+1];
    const float pz = pos[3*(base+t)+2];
    const unsigned int kb =
        __float_as_uint(__fsqrt_rn(__fadd_rn(__fmul_rn(px,px), __fmul_rn(py,py))));

    // ---- radix select KPOS-th smallest: 3 passes (11/11/10 bits) ----
    {
        const int shifts[3] = {21, 10, 0};
        const int bitsv [3] = {11, 11, 10};
        #pragma unroll 1
        for (int p = 0; p < 3; p++) {
            const int shift = shifts[p];
            const int nb = 1 << bitsv[p];
            hist[t] = 0u; hist[t + 1024] = 0u;
            __syncthreads();
            const unsigned int prefix = sstate[0], kth = sstate[1];
            const int sb = shift + bitsv[p];
            const unsigned int hm = (sb >= 32) ? 0u : (0xFFFFFFFFu << sb);
            if ((kb & hm) == prefix)
                atomicAdd(&hist[(kb >> shift) & (nb - 1)], 1u);
            __syncthreads();

            // parallel prefix over 2048 bins: thread owns bins {2t, 2t+1}
            const unsigned int h0 = hist[2 * t];
            const unsigned int h1 = hist[2 * t + 1];
            const unsigned int s = h0 + h1;
            unsigned int inc = s;
            #pragma unroll
            for (int d = 1; d < 32; d <<= 1) {
                unsigned int v = __shfl_up_sync(FULLMASK, inc, d);
                if (lane >= d) inc += v;
            }
            if (lane == 31) wA[w] = inc;
            __syncthreads();
            if (t < 32) {
                unsigned int wv = wA[t];
                unsigned int winc = wv;
                #pragma unroll
                for (int d = 1; d < 32; d <<= 1) {
                    unsigned int v = __shfl_up_sync(FULLMASK, winc, d);
                    if (t >= d) winc += v;
                }
                wA[t] = winc - wv;
            }
            __syncthreads();
            const unsigned int base0 = wA[w] + (inc - s);
            if (kth > base0 && kth <= base0 + h0) {
                sstate[0] = prefix | ((unsigned int)(2 * t) << shift);
                sstate[1] = kth - base0;
            } else if (kth > base0 + h0 && kth <= base0 + h0 + h1) {
                sstate[0] = prefix | ((unsigned int)(2 * t + 1) << shift);
                sstate[1] = kth - base0 - h0;
            }
            __syncthreads();
        }
    }
    const unsigned int T = sstate[0];
    const unsigned int r = sstate[1];

    // ---- closed-form tie handling + compaction + seed, 2 barriers total ----
    const bool ltT  = (kb < T);
    const bool tied = (kb == T);
    const unsigned int balL = __ballot_sync(FULLMASK, ltT);
    const unsigned int balT = __ballot_sync(FULLMASK, tied);
    if (lane == 0) { wA[w] = __popc(balL); wB[w] = __popc(balT); }

    ull pk = (((ull)kb) << 32) | (unsigned int)t;
    #pragma unroll
    for (int off = 16; off > 0; off >>= 1) {
        ull o2 = __shfl_xor_sync(FULLMASK, pk, off);
        if (o2 < pk) pk = o2;
    }
    if (lane == 0) wpk[w] = pk;
    __syncthreads();
    if (t < 32) {
        unsigned int a0 = wA[t], b0 = wB[t];
        unsigned int ia = a0, ib = b0;
        #pragma unroll
        for (int d = 1; d < 32; d <<= 1) {
            unsigned int va = __shfl_up_sync(FULLMASK, ia, d);
            unsigned int vb = __shfl_up_sync(FULLMASK, ib, d);
            if (t >= d) { ia += va; ib += vb; }
        }
        wA[t] = ia - a0; wB[t] = ib - b0;

        ull v2 = wpk[t];
        #pragma unroll
        for (int off = 16; off > 0; off >>= 1) {
            ull o2 = __shfl_xor_sync(FULLMASK, v2, off);
            if (o2 < v2) v2 = o2;
        }
        if (t == 0) spk = v2;
    }
    __syncthreads();
    const unsigned int lm = (1u << lane) - 1u;
    const unsigned int cnt_lt = wA[w] + __popc(balL & lm);
    const unsigned int cnt_td = wB[w] + __popc(balT & lm);
    const bool sel = ltT || (tied && cnt_td < r);
    if (sel) {
        const int slot = (int)(cnt_lt + (cnt_td < r ? cnt_td : r));
        g_pts[b * KPOS + slot] = make_float4(px, py, pz, __int_as_float(t));
        if ((unsigned int)t == (unsigned int)(spk & 0xFFFFFFFFull))
            g_seed[b] = slot;
    }
}

// ============================================================================
// Kernel 2: TWO warps per submap (8 pts/lane in regs, packed f32x2 updates).
// Cross-warp argmax: 1 named barrier/step + double-buffered smem slot.
// Block = 128 threads = 2 submaps; warp0 of each pair runs the MLP.
// ============================================================================
__global__ __launch_bounds__(128)
void fps_mlp_kernel(const float* __restrict__ x,
                    const float* __restrict__ W1, const float* __restrict__ b1,
                    const float* __restrict__ W2, const float* __restrict__ b2,
                    const float* __restrict__ W3, const float* __restrict__ b3,
                    float* __restrict__ out_w, float* __restrict__ out_i)
{
    __shared__ float4 qpos[2 * KPOS];
    __shared__ ull xw[2][2][2];   // [pair][buf][warp-in-pair]
    __shared__ float sW1[512]; __shared__ float sb1[16];
    __shared__ float sW2[128]; __shared__ float sb2[8];
    __shared__ float sW3[8];   __shared__ float sb3v;

    const int tid = threadIdx.x;
    for (int i = tid; i < 512; i += 128) sW1[i] = W1[i];
    if (tid < 128) sW2[tid] = W2[tid];
    if (tid < 16)  sb1[tid] = b1[tid];
    if (tid < 8)   sb2[tid] = b2[tid];
    if (tid < 8)   sW3[tid] = W3[tid];
    if (tid == 0)  sb3v = b3[0];
    __syncthreads();

    const int w = tid >> 5, lane = tid & 31;
    const int pair = w >> 1, ww = w & 1;
    const int b = blockIdx.x * 2 + pair;
    const int barid = 1 + pair;
    const int pbase = ww * 32 + lane;   // this lane's slot stride base

    const float4* bp = g_pts + (size_t)b * KPOS;
    float4* qp = qpos + pair * KPOS;

    ull pxp[4], pyp[4], pzp[4];
    float md[8];
    #pragma unroll
    for (int k = 0; k < 4; k++) {
        const float4 v0 = bp[(2*k)     * 64 + pbase];
        const float4 v1 = bp[(2*k + 1) * 64 + pbase];
        qp[(2*k)     * 64 + pbase] = v0;
        qp[(2*k + 1) * 64 + pbase] = v1;
        pxp[k] = pk2(v0.x, v1.x);
        pyp[k] = pk2(v0.y, v1.y);
        pzp[k] = pk2(v0.z, v1.z);
    }
    asm volatile("bar.sync %0, %1;" :: "r"(barid), "r"(64) : "memory");

    const int s0 = g_seed[b];
    float4 q = qp[s0];
    int mysel = s0;   // warp0 lane 'step' records the step'th selection

    // initial md = d2 to seed
    {
        const ull qnx = pk2(-q.x, -q.x), qny = pk2(-q.y, -q.y), qnz = pk2(-q.z, -q.z);
        #pragma unroll
        for (int k = 0; k < 4; k++) {
            const ull dx = addx2(pxp[k], qnx);
            const ull dy = addx2(pyp[k], qny);
            const ull dz = addx2(pzp[k], qnz);
            const ull d2 = addx2(addx2(mulx2(dx,dx), mulx2(dy,dy)), mulx2(dz,dz));
            upk2(d2, md[2*k], md[2*k+1]);
        }
    }

    #pragma unroll 1
    for (int step = 1; step < KSEL; step++) {
        // local argmax over 8 owned points (slots ascend with k: strict > keeps lowest)
        float best = md[0]; int bs = pbase;
        #pragma unroll
        for (int j = 1; j < 8; j++) {
            const int s = j * 64 + pbase;
            if (md[j] > best) { best = md[j]; bs = s; }
        }
        const unsigned int bb = __float_as_uint(best);
        const unsigned int wm = __reduce_max_sync(FULLMASK, bb);
        const unsigned int cand = (bb == wm) ? (unsigned int)bs : 0xFFFFFFFFu;
        const unsigned int ws = __reduce_min_sync(FULLMASK, cand);
        const int buf = step & 1;
        if (lane == 0)
            xw[pair][buf][ww] = (((ull)wm) << 32) | (unsigned int)(~ws);
        asm volatile("bar.sync %0, %1;" :: "r"(barid), "r"(64) : "memory");
        const ull p0 = xw[pair][buf][0];
        const ull p1 = xw[pair][buf][1];
        const ull win = (p0 > p1) ? p0 : p1;   // max dist, tie -> min slot
        const int cur = (int)(~(unsigned int)(win & 0xFFFFFFFFull));
        if (ww == 0 && lane == step) mysel = cur;
        q = qp[cur];
        const ull qnx = pk2(-q.x, -q.x), qny = pk2(-q.y, -q.y), qnz = pk2(-q.z, -q.z);
        #pragma unroll
        for (int k = 0; k < 4; k++) {
            const ull dx = addx2(pxp[k], qnx);
            const ull dy = addx2(pyp[k], qny);
            const ull dz = addx2(pzp[k], qnz);
            const ull d2 = addx2(addx2(mulx2(dx,dx), mulx2(dy,dy)), mulx2(dz,dz));
            float a, c2;
            upk2(d2, a, c2);
            md[2*k]   = fminf(md[2*k],   a);
            md[2*k+1] = fminf(md[2*k+1], c2);
        }
    }

    // ---- per-lane MLP (warp0 of each pair; lane = selection step) ----
    if (ww == 0) {
        const float4 qs = qp[mysel];
        const int o = __float_as_int(qs.w);
        const float* xr = x + ((long)b * NPTS + o) * 32;

        float h1[16];
        #pragma unroll
        for (int k2 = 0; k2 < 16; k2++) h1[k2] = sb1[k2];
        #pragma unroll
        for (int i = 0; i < 32; i += 4) {
            const float4 xv = *(const float4*)(xr + i);
            #pragma unroll
            for (int k2 = 0; k2 < 16; k2++) {
                h1[k2] = fmaf(xv.x, sW1[(i+0) * 16 + k2], h1[k2]);
                h1[k2] = fmaf(xv.y, sW1[(i+1) * 16 + k2], h1[k2]);
                h1[k2] = fmaf(xv.z, sW1[(i+2) * 16 + k2], h1[k2]);
                h1[k2] = fmaf(xv.w, sW1[(i+3) * 16 + k2], h1[k2]);
            }
        }
        #pragma unroll
        for (int k2 = 0; k2 < 16; k2++) h1[k2] = fmaxf(h1[k2], 0.f);

        float h2[8];
        #pragma unroll
        for (int k2 = 0; k2 < 8; k2++) h2[k2] = sb2[k2];
        #pragma unroll
        for (int j = 0; j < 16; j++) {
            const float hj = h1[j];
            #pragma unroll
            for (int k2 = 0; k2 < 8; k2++)
                h2[k2] = fmaf(hj, sW2[j * 8 + k2], h2[k2]);
        }
        float acc = sb3v;
        #pragma unroll
        for (int j = 0; j < 8; j++)
            acc = fmaf(fmaxf(h2[j], 0.f), sW3[j], acc);

        const float s = fmaxf(acc, 0.f) + log1pf(expf(-fabsf(acc)));

        out_w[b * KSEL + lane] = s;
        out_i[b * KSEL + lane] = (float)o;
    }
}

extern "C" void kernel_launch(void* const* d_in, const int* in_sizes, int n_in,
                              void* d_out, int out_size)
{
    const float* x   = (const float*)d_in[0];
    const float* pos = (const float*)d_in[1];
    // d_in[2] = batch (unused; regular layout)
    const float* W1 = (const float*)d_in[3];
    const float* b1 = (const float*)d_in[4];
    const float* W2 = (const float*)d_in[5];
    const float* b2 = (const float*)d_in[6];
    const float* W3 = (const float*)d_in[7];
    const float* b3 = (const float*)d_in[8];

    const int B = in_sizes[2] / NPTS;   // 2048
    float* out_w = (float*)d_out;
    float* out_i = out_w + (size_t)B * KSEL;

    select_kernel<<<B, NPTS>>>(pos);
    fps_mlp_kernel<<<B / 2, 128>>>(x, W1, b1, W2, b2, W3, b3, out_w, out_i);
}